// round 1
// baseline (speedup 1.0000x reference)
#include <cuda_runtime.h>
#include <math.h>
#include <stdint.h>

#define C 128
#define HID 64
#define MIXD 640
#define E_MAX 100000
#define N_MAX 10000
#define TB 256

typedef unsigned long long u64;

// ---------------- scratch (static device arrays: allocation-free) ----------
__device__ float g_mix[(size_t)E_MAX * MIXD];   // 256 MB
__device__ float g_geo[(size_t)E_MAX * 12];     // rn(3) + sqrt3*(rn rn^T - I/3)(9)
__device__ int   g_cnt[N_MAX];
__device__ int   g_cur[N_MAX];
__device__ int   g_off[N_MAX + 1];
__device__ int   g_csr[E_MAX];

// ---------------- f32x2 helpers --------------------------------------------
__device__ __forceinline__ u64 pk2(float x) {
    u64 r; asm("mov.b64 %0,{%1,%1};" : "=l"(r) : "f"(x)); return r;
}
__device__ __forceinline__ void fma2(u64& d, u64 a, u64 b) {
    asm("fma.rn.f32x2 %0, %1, %2, %0;" : "+l"(d) : "l"(a), "l"(b));
}
__device__ __forceinline__ float2 upk(u64 v) {
    float2 r; asm("mov.b64 {%0,%1}, %2;" : "=f"(r.x), "=f"(r.y) : "l"(v)); return r;
}
__device__ __forceinline__ float siluf(float x) { return x / (1.0f + expf(-x)); }

// dense layer: out[j] = silu( scale * sum_k in[k]*W[k*64+j] ), j in [0,64)
template <int KD>
__device__ __forceinline__ void dense64(const float* __restrict__ W,
                                        const float* in, float* out, float scale) {
#pragma unroll
    for (int t = 0; t < 2; t++) {
        u64 acc[16];
#pragma unroll
        for (int i = 0; i < 16; i++) acc[i] = 0ull;
#pragma unroll
        for (int k = 0; k < KD; k++) {
            u64 hk = pk2(in[k]);
            const ulonglong2* w = (const ulonglong2*)(W + k * 64 + t * 32);
#pragma unroll
            for (int p = 0; p < 8; p++) {
                ulonglong2 u = w[p];
                fma2(acc[2 * p], u.x, hk);
                fma2(acc[2 * p + 1], u.y, hk);
            }
        }
#pragma unroll
        for (int i = 0; i < 16; i++) {
            float2 f = upk(acc[i]);
            out[t * 32 + 2 * i]     = siluf(f.x * scale);
            out[t * 32 + 2 * i + 1] = siluf(f.y * scale);
        }
    }
}

// ---------------- CSR construction -----------------------------------------
__global__ void k_init(int N) {
    int i = blockIdx.x * blockDim.x + threadIdx.x;
    if (i < N) { g_cnt[i] = 0; g_cur[i] = 0; }
}
__global__ void k_hist(const int* __restrict__ recv, int E) {
    int i = blockIdx.x * blockDim.x + threadIdx.x;
    if (i < E) atomicAdd(&g_cnt[recv[i]], 1);
}
__global__ void k_scan(int N) {
    __shared__ int wsum[32];
    int tid = threadIdx.x, lane = tid & 31, wid = tid >> 5;
    int per = (N + 1023) >> 10;
    int st = tid * per, en = min(st + per, N);
    int s = 0;
    for (int i = st; i < en; i++) s += g_cnt[i];
    int v = s;
#pragma unroll
    for (int o = 1; o < 32; o <<= 1) {
        int u = __shfl_up_sync(0xffffffffu, v, o);
        if (lane >= o) v += u;
    }
    if (lane == 31) wsum[wid] = v;
    __syncthreads();
    if (wid == 0) {
        int w = wsum[lane];
#pragma unroll
        for (int o = 1; o < 32; o <<= 1) {
            int u = __shfl_up_sync(0xffffffffu, w, o);
            if (lane >= o) w += u;
        }
        wsum[lane] = w;  // inclusive scan of warp sums
    }
    __syncthreads();
    int base = (wid > 0 ? wsum[wid - 1] : 0) + (v - s);
    int run = base;
    for (int i = st; i < en; i++) { g_off[i] = run; run += g_cnt[i]; }
    if (tid == 1023) g_off[N] = run;
}
__global__ void k_scatter(const int* __restrict__ recv, int E) {
    int i = blockIdx.x * blockDim.x + threadIdx.x;
    if (i < E) {
        int r = recv[i];
        int p = atomicAdd(&g_cur[r], 1);
        g_csr[g_off[r] + p] = i;
    }
}

// ---------------- per-edge MLP + geometry ----------------------------------
// SMEM: w0(512) w1(4096) w2(4096) w3(40960) floats + stage(TB*32 floats)
#define SMEM_FLOATS (49664 + TB * 32)
#define SMEM_BYTES (SMEM_FLOATS * 4)

__global__ void __launch_bounds__(TB, 1) k_mlp(
    const float* __restrict__ vectors, const float* __restrict__ radial,
    const float* __restrict__ w0, const float* __restrict__ w1,
    const float* __restrict__ w2, const float* __restrict__ w3, int E) {
    extern __shared__ float smf[];
    float* w0s = smf;
    float* w1s = smf + 512;
    float* w2s = smf + 4608;
    float* w3s = smf + 8704;
    float* stage = smf + 49664;
    int tid = threadIdx.x;

    {   // cooperative weight load (float4)
        float4* d; const float4* s;
        d = (float4*)w0s; s = (const float4*)w0;
        for (int i = tid; i < 128; i += TB) d[i] = s[i];
        d = (float4*)w1s; s = (const float4*)w1;
        for (int i = tid; i < 1024; i += TB) d[i] = s[i];
        d = (float4*)w2s; s = (const float4*)w2;
        for (int i = tid; i < 1024; i += TB) d[i] = s[i];
        d = (float4*)w3s; s = (const float4*)w3;
        for (int i = tid; i < 10240; i += TB) d[i] = s[i];
    }

    int e0 = blockIdx.x * TB;
    int e = e0 + tid;
    int ec = min(e, E - 1);
    bool valid = (e < E);

    // geometry: rn and Y2' = sqrt(3)*(rn rn^T - I/3)   (CG constants folded)
    {
        float x = vectors[(size_t)ec * 3 + 0];
        float y = vectors[(size_t)ec * 3 + 1];
        float z = vectors[(size_t)ec * 3 + 2];
        float inv = rsqrtf(x * x + y * y + z * z);
        float r0 = x * inv, r1 = y * inv, r2 = z * inv;
        const float SQ3 = 1.7320508075688772f;
        if (valid) {
            float* G = g_geo + (size_t)e * 12;
            G[0] = r0; G[1] = r1; G[2] = r2;
            G[3] = SQ3 * (r0 * r0 - (1.f / 3.f));
            G[4] = SQ3 * r0 * r1;
            G[5] = SQ3 * r0 * r2;
            G[6] = SQ3 * r1 * r0;
            G[7] = SQ3 * (r1 * r1 - (1.f / 3.f));
            G[8] = SQ3 * r1 * r2;
            G[9] = SQ3 * r2 * r0;
            G[10] = SQ3 * r2 * r1;
            G[11] = SQ3 * (r2 * r2 - (1.f / 3.f));
        }
    }

    float rin[8];
    {
        const float4* rp = (const float4*)(radial + (size_t)ec * 8);
        float4 a4 = rp[0], b4 = rp[1];
        rin[0] = a4.x; rin[1] = a4.y; rin[2] = a4.z; rin[3] = a4.w;
        rin[4] = b4.x; rin[5] = b4.y; rin[6] = b4.z; rin[7] = b4.w;
    }
    __syncthreads();  // weights visible

    float a[64], b[64];
    dense64<8>(w0s, rin, a, 0.35355339059327373f);  // /sqrt(8)
    dense64<64>(w1s, a, b, 0.125f);                 // /sqrt(64)
    dense64<64>(w2s, b, a, 0.125f);
#pragma unroll
    for (int k = 0; k < 64; k++) a[k] *= 0.125f;    // fold w3's /8 (exact pow2)

    // mix = h @ w3, 20 tiles of 32 columns, staged for coalesced stores
    int nv = min(TB, E - e0);
    for (int t = 0; t < 20; t++) {
        u64 acc[16];
#pragma unroll
        for (int i = 0; i < 16; i++) acc[i] = 0ull;
#pragma unroll
        for (int k = 0; k < 64; k++) {
            u64 hk = pk2(a[k]);
            const ulonglong2* w = (const ulonglong2*)(w3s + k * MIXD + t * 32);
#pragma unroll
            for (int p = 0; p < 8; p++) {
                ulonglong2 u = w[p];
                fma2(acc[2 * p], u.x, hk);
                fma2(acc[2 * p + 1], u.y, hk);
            }
        }
        __syncthreads();  // previous tile's copy done
        u64* st = (u64*)stage;
#pragma unroll
        for (int i = 0; i < 16; i++) st[tid * 16 + (i ^ (tid & 15))] = acc[i];
        __syncthreads();
        const float* sf = (const float*)stage;
        for (int idx = tid; idx < nv * 32; idx += TB) {
            int ee = idx >> 5, jj = idx & 31;
            int s2 = (jj >> 1) ^ (ee & 15);
            g_mix[(size_t)(e0 + ee) * MIXD + t * 32 + jj] =
                sf[ee * 32 + s2 * 2 + (jj & 1)];
        }
    }
}

// ---------------- per-node gather/accumulate --------------------------------
__global__ void __launch_bounds__(128) k_node(
    const float* __restrict__ nf, const int* __restrict__ senders,
    float* __restrict__ out) {
    int n = blockIdx.x;
    int c = threadIdx.x;
    int beg = g_off[n], end = g_off[n + 1];
    float as0 = 0.f, as1 = 0.f;
    float av0 = 0.f, av1 = 0.f, av2 = 0.f;
    float aw0 = 0.f, aw1 = 0.f, aw2 = 0.f;
    float au0 = 0.f, au1 = 0.f, au2 = 0.f;
    for (int p = beg; p < end; p++) {
        int e = g_csr[p];
        int s = senders[e];
        const float* fr = nf + (size_t)s * 512;
        float ss = fr[c];
        float v0 = fr[128 + c * 3 + 0];
        float v1 = fr[128 + c * 3 + 1];
        float v2 = fr[128 + c * 3 + 2];
        const float4* G = (const float4*)(g_geo + (size_t)e * 12);
        float4 ga = G[0], gb = G[1], gc4 = G[2];
        const float* mx = g_mix + (size_t)e * MIXD;
        float m0 = mx[c], m1 = mx[C + c], m2 = mx[2 * C + c],
              m3 = mx[3 * C + c], m4 = mx[4 * C + c];
        float r0 = ga.x, r1 = ga.y, r2 = ga.z;
        float y00 = ga.w, y01 = gb.x, y02 = gb.y, y11 = gb.w,
              y12 = gc4.x, y22 = gc4.w;
        float tp0 = v0 * r0 + v1 * r1 + v2 * r2;      // CG*SH = 1
        as0 += ss * m0;
        as1 += tp0 * m1;
        av0 += v0 * m2; av1 += v1 * m2; av2 += v2 * m2;
        float sm3 = ss * m3;                           // tp1 = ss*rn
        aw0 += sm3 * r0; aw1 += sm3 * r1; aw2 += sm3 * r2;
        float t0 = y00 * v0 + y01 * v1 + y02 * v2;     // Y2' @ v
        float t1 = y01 * v0 + y11 * v1 + y12 * v2;
        float t2 = y02 * v0 + y12 * v1 + y22 * v2;
        au0 += t0 * m4; au1 += t1 * m4; au2 += t2 * m4;
    }
    const float sc = 0.31622776601683794f;  // 1/sqrt(10)
    float* ob = out + (size_t)n * 1408;
    ob[c] = as0 * sc;
    ob[C + c] = as1 * sc;
    ob[256 + c * 3 + 0] = av0 * sc;
    ob[256 + c * 3 + 1] = av1 * sc;
    ob[256 + c * 3 + 2] = av2 * sc;
    ob[640 + c * 3 + 0] = aw0 * sc;
    ob[640 + c * 3 + 1] = aw1 * sc;
    ob[640 + c * 3 + 2] = aw2 * sc;
    ob[1024 + c * 3 + 0] = au0 * sc;
    ob[1024 + c * 3 + 1] = au1 * sc;
    ob[1024 + c * 3 + 2] = au2 * sc;
}

// ---------------- launch -----------------------------------------------------
extern "C" void kernel_launch(void* const* d_in, const int* in_sizes, int n_in,
                              void* d_out, int out_size) {
    const float* vectors    = (const float*)d_in[0];
    const float* node_feats = (const float*)d_in[1];
    const float* radial     = (const float*)d_in[2];
    const float* w0         = (const float*)d_in[3];
    const float* w1         = (const float*)d_in[4];
    const float* w2         = (const float*)d_in[5];
    const float* w3         = (const float*)d_in[6];
    const int*   senders    = (const int*)d_in[7];
    const int*   receivers  = (const int*)d_in[8];
    float* out = (float*)d_out;

    int E = in_sizes[0] / 3;
    int N = in_sizes[1] / 512;

    cudaFuncSetAttribute(k_mlp, cudaFuncAttributeMaxDynamicSharedMemorySize,
                         SMEM_BYTES);

    k_init<<<(N + 255) / 256, 256>>>(N);
    k_hist<<<(E + 255) / 256, 256>>>(receivers, E);
    k_scan<<<1, 1024>>>(N);
    k_scatter<<<(E + 255) / 256, 256>>>(receivers, E);
    k_mlp<<<(E + TB - 1) / TB, TB, SMEM_BYTES>>>(vectors, radial, w0, w1, w2,
                                                 w3, E);
    k_node<<<N, 128>>>(node_feats, senders, out);
}

// round 3
// speedup vs baseline: 1.8203x; 1.8203x over previous
#include <cuda_runtime.h>
#include <cuda_bf16.h>
#include <cuda_fp16.h>
#include <math.h>
#include <stdint.h>

#define C 128
#define MIXD 640
#define E_MAX 100000
#define N_MAX 10000

typedef unsigned long long u64;

// ---------------- scratch (static device arrays: allocation-free) ----------
__device__ __half g_mix[(size_t)E_MAX * MIXD];      // 128 MB fp16
__device__ float  g_geo[(size_t)E_MAX * 12];
__device__ __nv_bfloat16 g_w3t_hi[MIXD * 64];       // w3^T * 0.125, bf16 hi
__device__ __nv_bfloat16 g_w3t_lo[MIXD * 64];       // residual
__device__ int g_cnt[N_MAX];
__device__ int g_cur[N_MAX];
__device__ int g_off[N_MAX + 1];
__device__ int g_csr[E_MAX];

// ---------------- f32x2 helpers --------------------------------------------
__device__ __forceinline__ u64 pk2(float x) {
    u64 r; asm("mov.b64 %0,{%1,%1};" : "=l"(r) : "f"(x)); return r;
}
__device__ __forceinline__ void fma2(u64& d, u64 a, u64 b) {
    asm("fma.rn.f32x2 %0, %1, %2, %0;" : "+l"(d) : "l"(a), "l"(b));
}
__device__ __forceinline__ float2 upk(u64 v) {
    float2 r; asm("mov.b64 {%0,%1}, %2;" : "=f"(r.x), "=f"(r.y) : "l"(v)); return r;
}
__device__ __forceinline__ float siluf(float x) { return x / (1.0f + expf(-x)); }

template <int KD>
__device__ __forceinline__ void dense64(const float* __restrict__ W,
                                        const float* in, float* out, float scale) {
#pragma unroll
    for (int t = 0; t < 2; t++) {
        u64 acc[16];
#pragma unroll
        for (int i = 0; i < 16; i++) acc[i] = 0ull;
#pragma unroll
        for (int k = 0; k < KD; k++) {
            u64 hk = pk2(in[k]);
            const ulonglong2* w = (const ulonglong2*)(W + k * 64 + t * 32);
#pragma unroll
            for (int p = 0; p < 8; p++) {
                ulonglong2 u = w[p];
                fma2(acc[2 * p], u.x, hk);
                fma2(acc[2 * p + 1], u.y, hk);
            }
        }
#pragma unroll
        for (int i = 0; i < 16; i++) {
            float2 f = upk(acc[i]);
            out[t * 32 + 2 * i]     = siluf(f.x * scale);
            out[t * 32 + 2 * i + 1] = siluf(f.y * scale);
        }
    }
}

// ---------------- mma / ldmatrix helpers (arch-generic, sm_80+) ------------
__device__ __forceinline__ uint32_t smem_u32(const void* p) {
    uint32_t a;
    asm("{ .reg .u64 t; cvta.to.shared.u64 t, %1; cvt.u32.u64 %0, t; }"
        : "=r"(a) : "l"(p));
    return a;
}
__device__ __forceinline__ void ldm_x4(uint32_t* r, uint32_t addr) {
    asm volatile("ldmatrix.sync.aligned.m8n8.x4.shared.b16 {%0,%1,%2,%3}, [%4];"
                 : "=r"(r[0]), "=r"(r[1]), "=r"(r[2]), "=r"(r[3]) : "r"(addr));
}
__device__ __forceinline__ void mma_bf16(float* d, const uint32_t* a,
                                         const uint32_t* b) {
    asm volatile(
        "mma.sync.aligned.m16n8k16.row.col.f32.bf16.bf16.f32 "
        "{%0,%1,%2,%3}, {%4,%5,%6,%7}, {%8,%9}, {%0,%1,%2,%3};"
        : "+f"(d[0]), "+f"(d[1]), "+f"(d[2]), "+f"(d[3])
        : "r"(a[0]), "r"(a[1]), "r"(a[2]), "r"(a[3]), "r"(b[0]), "r"(b[1]));
}

// ---------------- CSR construction -----------------------------------------
__global__ void k_init(int N) {
    int i = blockIdx.x * blockDim.x + threadIdx.x;
    if (i < N) { g_cnt[i] = 0; g_cur[i] = 0; }
}
__global__ void k_hist(const int* __restrict__ recv, int E) {
    int i = blockIdx.x * blockDim.x + threadIdx.x;
    if (i < E) atomicAdd(&g_cnt[recv[i]], 1);
}
__global__ void k_scan(int N) {
    __shared__ int wsum[32];
    int tid = threadIdx.x, lane = tid & 31, wid = tid >> 5;
    int per = (N + 1023) >> 10;
    int st = tid * per, en = min(st + per, N);
    int s = 0;
    for (int i = st; i < en; i++) s += g_cnt[i];
    int v = s;
#pragma unroll
    for (int o = 1; o < 32; o <<= 1) {
        int u = __shfl_up_sync(0xffffffffu, v, o);
        if (lane >= o) v += u;
    }
    if (lane == 31) wsum[wid] = v;
    __syncthreads();
    if (wid == 0) {
        int w = wsum[lane];
#pragma unroll
        for (int o = 1; o < 32; o <<= 1) {
            int u = __shfl_up_sync(0xffffffffu, w, o);
            if (lane >= o) w += u;
        }
        wsum[lane] = w;
    }
    __syncthreads();
    int base = (wid > 0 ? wsum[wid - 1] : 0) + (v - s);
    int run = base;
    for (int i = st; i < en; i++) { g_off[i] = run; run += g_cnt[i]; }
    if (tid == 1023) g_off[N] = run;
}
__global__ void k_scatter(const int* __restrict__ recv, int E) {
    int i = blockIdx.x * blockDim.x + threadIdx.x;
    if (i < E) {
        int r = recv[i];
        int p = atomicAdd(&g_cur[r], 1);
        g_csr[g_off[r] + p] = i;
    }
}

// ---------------- w3 transpose + bf16 split (scale 1/8 folded) -------------
__global__ void k_w3t(const float* __restrict__ w3) {
    int i = blockIdx.x * blockDim.x + threadIdx.x;
    if (i >= MIXD * 64) return;
    int n = i >> 6, k = i & 63;
    float v = w3[k * MIXD + n] * 0.125f;
    __nv_bfloat16 hi = __float2bfloat16_rn(v);
    float lo = v - __bfloat162float(hi);
    g_w3t_hi[i] = hi;
    g_w3t_lo[i] = __float2bfloat16_rn(lo);
}

// ---------------- per-edge MLP + HMMA GEMM ----------------------------------
// SMEM map (bytes). A/B rows padded to 144 B (144 mod 128 = 16: ldmatrix
// conflict-free).
#define SM_W0   0         // 512 f   (2048 B)
#define SM_W1   2048      // 4096 f  (16384 B)
#define SM_W2   18432     // 4096 f  (16384 B)
#define SM_AHI  34816     // 256 rows x 144 B = 36864
#define SM_ALO  71680
#define SM_BHI  108544    // 80 rows x 144 B = 11520
#define SM_BLO  120064
#define SM_TOTAL 131584

__global__ void __launch_bounds__(256, 1) k_mlp(
    const float* __restrict__ vectors, const float* __restrict__ radial,
    const float* __restrict__ w0, const float* __restrict__ w1,
    const float* __restrict__ w2, int E) {
    extern __shared__ char sm[];
    int tid = threadIdx.x;
    int w = tid >> 5, lane = tid & 31;

    {   // cooperative weight load
        float4* d; const float4* s;
        d = (float4*)(sm + SM_W0); s = (const float4*)w0;
        for (int i = tid; i < 128; i += 256) d[i] = s[i];
        d = (float4*)(sm + SM_W1); s = (const float4*)w1;
        for (int i = tid; i < 1024; i += 256) d[i] = s[i];
        d = (float4*)(sm + SM_W2); s = (const float4*)w2;
        for (int i = tid; i < 1024; i += 256) d[i] = s[i];
    }

    int e0 = blockIdx.x * 256;
    int e = e0 + tid;
    int ec = min(e, E - 1);
    bool valid = (e < E);

    // geometry
    {
        float x = vectors[(size_t)ec * 3 + 0];
        float y = vectors[(size_t)ec * 3 + 1];
        float z = vectors[(size_t)ec * 3 + 2];
        float inv = rsqrtf(x * x + y * y + z * z);
        float r0 = x * inv, r1 = y * inv, r2 = z * inv;
        const float SQ3 = 1.7320508075688772f;
        if (valid) {
            float* G = g_geo + (size_t)e * 12;
            G[0] = r0; G[1] = r1; G[2] = r2;
            G[3] = SQ3 * (r0 * r0 - (1.f / 3.f));
            G[4] = SQ3 * r0 * r1;
            G[5] = SQ3 * r0 * r2;
            G[6] = SQ3 * r1 * r0;
            G[7] = SQ3 * (r1 * r1 - (1.f / 3.f));
            G[8] = SQ3 * r1 * r2;
            G[9] = SQ3 * r2 * r0;
            G[10] = SQ3 * r2 * r1;
            G[11] = SQ3 * (r2 * r2 - (1.f / 3.f));
        }
    }

    float rin[8];
    {
        const float4* rp = (const float4*)(radial + (size_t)ec * 8);
        float4 a4 = rp[0], b4 = rp[1];
        rin[0] = a4.x; rin[1] = a4.y; rin[2] = a4.z; rin[3] = a4.w;
        rin[4] = b4.x; rin[5] = b4.y; rin[6] = b4.z; rin[7] = b4.w;
    }
    __syncthreads();

    float a[64], b[64];
    dense64<8>((const float*)(sm + SM_W0), rin, a, 0.35355339059327373f);
    dense64<64>((const float*)(sm + SM_W1), a, b, 0.125f);
    dense64<64>((const float*)(sm + SM_W2), b, a, 0.125f);

    // h -> bf16 hi/lo, write to padded SMEM rows (row = tid)
    {
        uint32_t hi2[32], lo2[32];
#pragma unroll
        for (int i = 0; i < 32; i++) {
            __nv_bfloat16 h0 = __float2bfloat16_rn(a[2 * i]);
            __nv_bfloat16 h1 = __float2bfloat16_rn(a[2 * i + 1]);
            float l0 = a[2 * i] - __bfloat162float(h0);
            float l1 = a[2 * i + 1] - __bfloat162float(h1);
            hi2[i] = (uint32_t)__bfloat16_as_ushort(h0) |
                     ((uint32_t)__bfloat16_as_ushort(h1) << 16);
            lo2[i] = (uint32_t)__bfloat16_as_ushort(__float2bfloat16_rn(l0)) |
                     ((uint32_t)__bfloat16_as_ushort(__float2bfloat16_rn(l1)) << 16);
        }
        char* rh = sm + SM_AHI + tid * 144;
        char* rl = sm + SM_ALO + tid * 144;
#pragma unroll
        for (int j = 0; j < 8; j++) {
            *(uint4*)(rh + 16 * j) = ((uint4*)hi2)[j];
            *(uint4*)(rl + 16 * j) = ((uint4*)lo2)[j];
        }
    }
    __syncthreads();

    // load A fragments (persistent): warp w owns edges 32w..32w+31 (2 m16 tiles)
    uint32_t aH[2][4][4], aL[2][4][4];
    {
        uint32_t Ah = smem_u32(sm + SM_AHI);
        uint32_t Al = smem_u32(sm + SM_ALO);
        int g = lane >> 3, rin8 = lane & 7;
#pragma unroll
        for (int mt = 0; mt < 2; mt++) {
            int row = 32 * w + 16 * mt + (g & 1) * 8 + rin8;
#pragma unroll
            for (int kt = 0; kt < 4; kt++) {
                uint32_t off = (uint32_t)row * 144 + kt * 32 + (g >> 1) * 16;
                ldm_x4(aH[mt][kt], Ah + off);
                ldm_x4(aL[mt][kt], Al + off);
            }
        }
    }

    uint32_t Bh = smem_u32(sm + SM_BHI);
    uint32_t Bl = smem_u32(sm + SM_BLO);
    int g = lane >> 3, rin8 = lane & 7;
    int m_lane = lane >> 2, n_lane = (lane & 3) * 2;

    // 8 chunks of 80 columns
    for (int cc = 0; cc < 8; cc++) {
        __syncthreads();  // previous chunk's mma done before overwrite
        // load B chunk: rows n = cc*80..+79, 8 x 16B segs per row
        for (int idx = tid; idx < 640; idx += 256) {
            int rown = idx >> 3, seg = idx & 7;
            const uint4* sh =
                (const uint4*)(g_w3t_hi + (size_t)(cc * 80 + rown) * 64) + seg;
            const uint4* sl =
                (const uint4*)(g_w3t_lo + (size_t)(cc * 80 + rown) * 64) + seg;
            *(uint4*)(sm + SM_BHI + rown * 144 + seg * 16) = *sh;
            *(uint4*)(sm + SM_BLO + rown * 144 + seg * 16) = *sl;
        }
        __syncthreads();

        float acc[2][10][4];
#pragma unroll
        for (int mt = 0; mt < 2; mt++)
#pragma unroll
            for (int nt = 0; nt < 10; nt++)
#pragma unroll
                for (int q = 0; q < 4; q++) acc[mt][nt][q] = 0.f;

#pragma unroll
        for (int nt = 0; nt < 10; nt++) {
            uint32_t bh[8], bl[8];
#pragma unroll
            for (int p = 0; p < 2; p++) {
                uint32_t off = (uint32_t)(nt * 8 + rin8) * 144 + p * 64 + g * 16;
                ldm_x4(&bh[p * 4], Bh + off);
                ldm_x4(&bl[p * 4], Bl + off);
            }
#pragma unroll
            for (int mt = 0; mt < 2; mt++) {
#pragma unroll
                for (int kt = 0; kt < 4; kt++) {
                    mma_bf16(acc[mt][nt], aH[mt][kt], &bh[kt * 2]);
                    mma_bf16(acc[mt][nt], aH[mt][kt], &bl[kt * 2]);
                    mma_bf16(acc[mt][nt], aL[mt][kt], &bh[kt * 2]);
                }
            }
        }

        // epilogue: fp32 acc -> fp16 g_mix
#pragma unroll
        for (int mt = 0; mt < 2; mt++) {
            int er = e0 + 32 * w + 16 * mt + m_lane;
#pragma unroll
            for (int nt = 0; nt < 10; nt++) {
                int col = cc * 80 + nt * 8 + n_lane;
                float* q = acc[mt][nt];
                if (er < E)
                    *(__half2*)(g_mix + (size_t)er * MIXD + col) =
                        __floats2half2_rn(q[0], q[1]);
                if (er + 8 < E)
                    *(__half2*)(g_mix + (size_t)(er + 8) * MIXD + col) =
                        __floats2half2_rn(q[2], q[3]);
            }
        }
    }
}

// ---------------- per-node gather/accumulate --------------------------------
__global__ void __launch_bounds__(128) k_node(
    const float* __restrict__ nf, const int* __restrict__ senders,
    float* __restrict__ out) {
    int n = blockIdx.x;
    int c = threadIdx.x;
    int beg = g_off[n], end = g_off[n + 1];
    float as0 = 0.f, as1 = 0.f;
    float av0 = 0.f, av1 = 0.f, av2 = 0.f;
    float aw0 = 0.f, aw1 = 0.f, aw2 = 0.f;
    float au0 = 0.f, au1 = 0.f, au2 = 0.f;
    for (int p = beg; p < end; p++) {
        int e = g_csr[p];
        int s = senders[e];
        const float* fr = nf + (size_t)s * 512;
        float ss = fr[c];
        float v0 = fr[128 + c * 3 + 0];
        float v1 = fr[128 + c * 3 + 1];
        float v2 = fr[128 + c * 3 + 2];
        const float4* G = (const float4*)(g_geo + (size_t)e * 12);
        float4 ga = G[0], gb = G[1], gc4 = G[2];
        const __half* mx = g_mix + (size_t)e * MIXD;
        float m0 = __half2float(mx[c]);
        float m1 = __half2float(mx[C + c]);
        float m2 = __half2float(mx[2 * C + c]);
        float m3 = __half2float(mx[3 * C + c]);
        float m4 = __half2float(mx[4 * C + c]);
        float r0 = ga.x, r1 = ga.y, r2 = ga.z;
        float y00 = ga.w, y01 = gb.x, y02 = gb.y, y11 = gb.w,
              y12 = gc4.x, y22 = gc4.w;
        float tp0 = v0 * r0 + v1 * r1 + v2 * r2;
        as0 += ss * m0;
        as1 += tp0 * m1;
        av0 += v0 * m2; av1 += v1 * m2; av2 += v2 * m2;
        float sm3 = ss * m3;
        aw0 += sm3 * r0; aw1 += sm3 * r1; aw2 += sm3 * r2;
        float t0 = y00 * v0 + y01 * v1 + y02 * v2;
        float t1 = y01 * v0 + y11 * v1 + y12 * v2;
        float t2 = y02 * v0 + y12 * v1 + y22 * v2;
        au0 += t0 * m4; au1 += t1 * m4; au2 += t2 * m4;
    }
    const float sc = 0.31622776601683794f;  // 1/sqrt(10)
    float* ob = out + (size_t)n * 1408;
    ob[c] = as0 * sc;
    ob[C + c] = as1 * sc;
    ob[256 + c * 3 + 0] = av0 * sc;
    ob[256 + c * 3 + 1] = av1 * sc;
    ob[256 + c * 3 + 2] = av2 * sc;
    ob[640 + c * 3 + 0] = aw0 * sc;
    ob[640 + c * 3 + 1] = aw1 * sc;
    ob[640 + c * 3 + 2] = aw2 * sc;
    ob[1024 + c * 3 + 0] = au0 * sc;
    ob[1024 + c * 3 + 1] = au1 * sc;
    ob[1024 + c * 3 + 2] = au2 * sc;
}

// ---------------- launch -----------------------------------------------------
extern "C" void kernel_launch(void* const* d_in, const int* in_sizes, int n_in,
                              void* d_out, int out_size) {
    const float* vectors    = (const float*)d_in[0];
    const float* node_feats = (const float*)d_in[1];
    const float* radial     = (const float*)d_in[2];
    const float* w0         = (const float*)d_in[3];
    const float* w1         = (const float*)d_in[4];
    const float* w2         = (const float*)d_in[5];
    const float* w3         = (const float*)d_in[6];
    const int*   senders    = (const int*)d_in[7];
    const int*   receivers  = (const int*)d_in[8];
    float* out = (float*)d_out;

    int E = in_sizes[0] / 3;
    int N = in_sizes[1] / 512;

    cudaFuncSetAttribute(k_mlp, cudaFuncAttributeMaxDynamicSharedMemorySize,
                         SM_TOTAL);

    k_init<<<(N + 255) / 256, 256>>>(N);
    k_hist<<<(E + 255) / 256, 256>>>(receivers, E);
    k_scan<<<1, 1024>>>(N);
    k_scatter<<<(E + 255) / 256, 256>>>(receivers, E);
    k_w3t<<<(MIXD * 64 + 255) / 256, 256>>>(w3);
    k_mlp<<<(E + 255) / 256, 256, SM_TOTAL>>>(vectors, radial, w0, w1, w2, E);
    k_node<<<N, 128>>>(node_feats, senders, out);
}

// round 4
// speedup vs baseline: 1.9605x; 1.0771x over previous
#include <cuda_runtime.h>
#include <cuda_bf16.h>
#include <cuda_fp16.h>
#include <math.h>
#include <stdint.h>

#define C 128
#define MIXD 640
#define E_MAX 100000
#define N_MAX 10000

typedef unsigned long long u64;

// ---------------- scratch (static device arrays: allocation-free) ----------
__device__ __half g_mix[(size_t)E_MAX * MIXD];      // 128 MB fp16
__device__ float  g_geo[(size_t)E_MAX * 12];
__device__ __half g_w3t[MIXD * 64];                 // w3^T * 0.125, fp16
__device__ int g_cnt[N_MAX];
__device__ int g_cur[N_MAX];
__device__ int g_off[N_MAX + 1];
__device__ int g_csr[E_MAX];

// ---------------- f32x2 helpers --------------------------------------------
__device__ __forceinline__ u64 pk2(float x) {
    u64 r; asm("mov.b64 %0,{%1,%1};" : "=l"(r) : "f"(x)); return r;
}
__device__ __forceinline__ void fma2(u64& d, u64 a, u64 b) {
    asm("fma.rn.f32x2 %0, %1, %2, %0;" : "+l"(d) : "l"(a), "l"(b));
}
__device__ __forceinline__ float2 upk(u64 v) {
    float2 r; asm("mov.b64 {%0,%1}, %2;" : "=f"(r.x), "=f"(r.y) : "l"(v)); return r;
}
__device__ __forceinline__ float siluf(float x) { return x / (1.0f + expf(-x)); }

template <int KD>
__device__ __forceinline__ void dense64(const float* __restrict__ W,
                                        const float* in, float* out, float scale) {
#pragma unroll
    for (int t = 0; t < 2; t++) {
        u64 acc[16];
#pragma unroll
        for (int i = 0; i < 16; i++) acc[i] = 0ull;
#pragma unroll
        for (int k = 0; k < KD; k++) {
            u64 hk = pk2(in[k]);
            const ulonglong2* w = (const ulonglong2*)(W + k * 64 + t * 32);
#pragma unroll
            for (int p = 0; p < 8; p++) {
                ulonglong2 u = w[p];
                fma2(acc[2 * p], u.x, hk);
                fma2(acc[2 * p + 1], u.y, hk);
            }
        }
#pragma unroll
        for (int i = 0; i < 16; i++) {
            float2 f = upk(acc[i]);
            out[t * 32 + 2 * i]     = siluf(f.x * scale);
            out[t * 32 + 2 * i + 1] = siluf(f.y * scale);
        }
    }
}

// ---------------- mma / ldmatrix helpers (arch-generic, sm_80+) ------------
__device__ __forceinline__ uint32_t smem_u32(const void* p) {
    uint32_t a;
    asm("{ .reg .u64 t; cvta.to.shared.u64 t, %1; cvt.u32.u64 %0, t; }"
        : "=r"(a) : "l"(p));
    return a;
}
__device__ __forceinline__ void ldm_x4(uint32_t* r, uint32_t addr) {
    asm volatile("ldmatrix.sync.aligned.m8n8.x4.shared.b16 {%0,%1,%2,%3}, [%4];"
                 : "=r"(r[0]), "=r"(r[1]), "=r"(r[2]), "=r"(r[3]) : "r"(addr));
}
__device__ __forceinline__ void mma_f16(float* d, const uint32_t* a,
                                        const uint32_t* b) {
    asm volatile(
        "mma.sync.aligned.m16n8k16.row.col.f32.f16.f16.f32 "
        "{%0,%1,%2,%3}, {%4,%5,%6,%7}, {%8,%9}, {%0,%1,%2,%3};"
        : "+f"(d[0]), "+f"(d[1]), "+f"(d[2]), "+f"(d[3])
        : "r"(a[0]), "r"(a[1]), "r"(a[2]), "r"(a[3]), "r"(b[0]), "r"(b[1]));
}

// ---------------- CSR construction -----------------------------------------
__global__ void k_init(int N) {
    int i = blockIdx.x * blockDim.x + threadIdx.x;
    if (i < N) { g_cnt[i] = 0; g_cur[i] = 0; }
}
__global__ void k_hist(const int* __restrict__ recv, int E) {
    int i = blockIdx.x * blockDim.x + threadIdx.x;
    if (i < E) atomicAdd(&g_cnt[recv[i]], 1);
}
__global__ void k_scan(int N) {
    __shared__ int wsum[32];
    int tid = threadIdx.x, lane = tid & 31, wid = tid >> 5;
    int per = (N + 1023) >> 10;
    int st = tid * per, en = min(st + per, N);
    int s = 0;
    for (int i = st; i < en; i++) s += g_cnt[i];
    int v = s;
#pragma unroll
    for (int o = 1; o < 32; o <<= 1) {
        int u = __shfl_up_sync(0xffffffffu, v, o);
        if (lane >= o) v += u;
    }
    if (lane == 31) wsum[wid] = v;
    __syncthreads();
    if (wid == 0) {
        int w = wsum[lane];
#pragma unroll
        for (int o = 1; o < 32; o <<= 1) {
            int u = __shfl_up_sync(0xffffffffu, w, o);
            if (lane >= o) w += u;
        }
        wsum[lane] = w;
    }
    __syncthreads();
    int base = (wid > 0 ? wsum[wid - 1] : 0) + (v - s);
    int run = base;
    for (int i = st; i < en; i++) { g_off[i] = run; run += g_cnt[i]; }
    if (tid == 1023) g_off[N] = run;
}
__global__ void k_scatter(const int* __restrict__ recv, int E) {
    int i = blockIdx.x * blockDim.x + threadIdx.x;
    if (i < E) {
        int r = recv[i];
        int p = atomicAdd(&g_cur[r], 1);
        g_csr[g_off[r] + p] = i;
    }
}

// ---------------- w3 transpose to fp16 (scale 1/8 folded) ------------------
__global__ void k_w3t(const float* __restrict__ w3) {
    int i = blockIdx.x * blockDim.x + threadIdx.x;
    if (i >= MIXD * 64) return;
    int n = i >> 6, k = i & 63;
    g_w3t[i] = __float2half_rn(w3[k * MIXD + n] * 0.125f);
}

// ---------------- per-edge MLP + HMMA GEMM (fp16 single-pass) ---------------
// Rows padded to 144 B (144 mod 128 = 16: ldmatrix conflict-free).
#define SM_W0   0         // 512 f   (2048 B)
#define SM_W1   2048      // 4096 f  (16384 B)
#define SM_W2   18432     // 4096 f  (16384 B)
#define SM_A    34816     // 256 rows x 144 B = 36864
#define SM_B    71680     // 80 rows x 144 B = 11520
#define SM_TOTAL 83200

__global__ void __launch_bounds__(256, 1) k_mlp(
    const float* __restrict__ vectors, const float* __restrict__ radial,
    const float* __restrict__ w0, const float* __restrict__ w1,
    const float* __restrict__ w2, int E) {
    extern __shared__ char sm[];
    int tid = threadIdx.x;
    int w = tid >> 5, lane = tid & 31;

    {   // cooperative weight load
        float4* d; const float4* s;
        d = (float4*)(sm + SM_W0); s = (const float4*)w0;
        for (int i = tid; i < 128; i += 256) d[i] = s[i];
        d = (float4*)(sm + SM_W1); s = (const float4*)w1;
        for (int i = tid; i < 1024; i += 256) d[i] = s[i];
        d = (float4*)(sm + SM_W2); s = (const float4*)w2;
        for (int i = tid; i < 1024; i += 256) d[i] = s[i];
    }

    int e0 = blockIdx.x * 256;
    int e = e0 + tid;
    int ec = min(e, E - 1);
    bool valid = (e < E);

    // geometry
    {
        float x = vectors[(size_t)ec * 3 + 0];
        float y = vectors[(size_t)ec * 3 + 1];
        float z = vectors[(size_t)ec * 3 + 2];
        float inv = rsqrtf(x * x + y * y + z * z);
        float r0 = x * inv, r1 = y * inv, r2 = z * inv;
        const float SQ3 = 1.7320508075688772f;
        if (valid) {
            float* G = g_geo + (size_t)e * 12;
            G[0] = r0; G[1] = r1; G[2] = r2;
            G[3] = SQ3 * (r0 * r0 - (1.f / 3.f));
            G[4] = SQ3 * r0 * r1;
            G[5] = SQ3 * r0 * r2;
            G[6] = SQ3 * r1 * r0;
            G[7] = SQ3 * (r1 * r1 - (1.f / 3.f));
            G[8] = SQ3 * r1 * r2;
            G[9] = SQ3 * r2 * r0;
            G[10] = SQ3 * r2 * r1;
            G[11] = SQ3 * (r2 * r2 - (1.f / 3.f));
        }
    }

    float rin[8];
    {
        const float4* rp = (const float4*)(radial + (size_t)ec * 8);
        float4 a4 = rp[0], b4 = rp[1];
        rin[0] = a4.x; rin[1] = a4.y; rin[2] = a4.z; rin[3] = a4.w;
        rin[4] = b4.x; rin[5] = b4.y; rin[6] = b4.z; rin[7] = b4.w;
    }
    __syncthreads();

    float a[64], b[64];
    dense64<8>((const float*)(sm + SM_W0), rin, a, 0.35355339059327373f);
    dense64<64>((const float*)(sm + SM_W1), a, b, 0.125f);
    dense64<64>((const float*)(sm + SM_W2), b, a, 0.125f);

    // h -> fp16, write to padded SMEM row (row = tid)
    {
        uint32_t h2[32];
#pragma unroll
        for (int i = 0; i < 32; i++) {
            __half2 p = __floats2half2_rn(a[2 * i], a[2 * i + 1]);
            h2[i] = *(uint32_t*)&p;
        }
        char* rh = sm + SM_A + tid * 144;
#pragma unroll
        for (int j = 0; j < 8; j++) *(uint4*)(rh + 16 * j) = ((uint4*)h2)[j];
    }
    __syncthreads();

    // persistent A fragments: warp w owns edges 32w..32w+31 (2 m16 tiles)
    uint32_t aF[2][4][4];
    {
        uint32_t Ab = smem_u32(sm + SM_A);
        int g = lane >> 3, r8 = lane & 7;
#pragma unroll
        for (int mt = 0; mt < 2; mt++) {
            int row = 32 * w + 16 * mt + (g & 1) * 8 + r8;
#pragma unroll
            for (int kt = 0; kt < 4; kt++)
                ldm_x4(aF[mt][kt], Ab + (uint32_t)row * 144 + kt * 32 + (g >> 1) * 16);
        }
    }

    uint32_t Bb = smem_u32(sm + SM_B);
    int g = lane >> 3, r8 = lane & 7;
    int m_lane = lane >> 2, n_lane = (lane & 3) * 2;

    // 8 chunks of 80 columns
    for (int cc = 0; cc < 8; cc++) {
        __syncthreads();  // previous chunk's mma done before overwrite
        for (int idx = tid; idx < 640; idx += 256) {
            int rown = idx >> 3, seg = idx & 7;
            *(uint4*)(sm + SM_B + rown * 144 + seg * 16) =
                *((const uint4*)(g_w3t + (size_t)(cc * 80 + rown) * 64) + seg);
        }
        __syncthreads();

#pragma unroll
        for (int nt = 0; nt < 10; nt++) {
            uint32_t bF[8];
#pragma unroll
            for (int p = 0; p < 2; p++)
                ldm_x4(&bF[p * 4],
                       Bb + (uint32_t)(nt * 8 + r8) * 144 + p * 64 + g * 16);

            float acc[2][4];
#pragma unroll
            for (int mt = 0; mt < 2; mt++) {
#pragma unroll
                for (int q = 0; q < 4; q++) acc[mt][q] = 0.f;
#pragma unroll
                for (int kt = 0; kt < 4; kt++)
                    mma_f16(acc[mt], aF[mt][kt], &bF[kt * 2]);
            }
            // immediate epilogue: fp32 -> fp16 g_mix
            int col = cc * 80 + nt * 8 + n_lane;
#pragma unroll
            for (int mt = 0; mt < 2; mt++) {
                int er = e0 + 32 * w + 16 * mt + m_lane;
                if (er < E)
                    *(__half2*)(g_mix + (size_t)er * MIXD + col) =
                        __floats2half2_rn(acc[mt][0], acc[mt][1]);
                if (er + 8 < E)
                    *(__half2*)(g_mix + (size_t)(er + 8) * MIXD + col) =
                        __floats2half2_rn(acc[mt][2], acc[mt][3]);
            }
        }
    }
}

// ---------------- per-node gather/accumulate --------------------------------
__global__ void __launch_bounds__(128) k_node(
    const float* __restrict__ nf, const int* __restrict__ senders,
    float* __restrict__ out) {
    int n = blockIdx.x;
    int c = threadIdx.x;
    int beg = g_off[n], end = g_off[n + 1];
    float as0 = 0.f, as1 = 0.f;
    float av0 = 0.f, av1 = 0.f, av2 = 0.f;
    float aw0 = 0.f, aw1 = 0.f, aw2 = 0.f;
    float au0 = 0.f, au1 = 0.f, au2 = 0.f;
    for (int p = beg; p < end; p++) {
        int e = g_csr[p];
        int s = senders[e];
        const float* fr = nf + (size_t)s * 512;
        float ss = fr[c];
        float v0 = fr[128 + c * 3 + 0];
        float v1 = fr[128 + c * 3 + 1];
        float v2 = fr[128 + c * 3 + 2];
        const float4* G = (const float4*)(g_geo + (size_t)e * 12);
        float4 ga = G[0], gb = G[1], gc4 = G[2];
        const __half* mx = g_mix + (size_t)e * MIXD;
        float m0 = __half2float(mx[c]);
        float m1 = __half2float(mx[C + c]);
        float m2 = __half2float(mx[2 * C + c]);
        float m3 = __half2float(mx[3 * C + c]);
        float m4 = __half2float(mx[4 * C + c]);
        float r0 = ga.x, r1 = ga.y, r2 = ga.z;
        float y00 = ga.w, y01 = gb.x, y02 = gb.y, y11 = gb.w,
              y12 = gc4.x, y22 = gc4.w;
        float tp0 = v0 * r0 + v1 * r1 + v2 * r2;
        as0 += ss * m0;
        as1 += tp0 * m1;
        av0 += v0 * m2; av1 += v1 * m2; av2 += v2 * m2;
        float sm3 = ss * m3;
        aw0 += sm3 * r0; aw1 += sm3 * r1; aw2 += sm3 * r2;
        float t0 = y00 * v0 + y01 * v1 + y02 * v2;
        float t1 = y01 * v0 + y11 * v1 + y12 * v2;
        float t2 = y02 * v0 + y12 * v1 + y22 * v2;
        au0 += t0 * m4; au1 += t1 * m4; au2 += t2 * m4;
    }
    const float sc = 0.31622776601683794f;  // 1/sqrt(10)
    float* ob = out + (size_t)n * 1408;
    ob[c] = as0 * sc;
    ob[C + c] = as1 * sc;
    ob[256 + c * 3 + 0] = av0 * sc;
    ob[256 + c * 3 + 1] = av1 * sc;
    ob[256 + c * 3 + 2] = av2 * sc;
    ob[640 + c * 3 + 0] = aw0 * sc;
    ob[640 + c * 3 + 1] = aw1 * sc;
    ob[640 + c * 3 + 2] = aw2 * sc;
    ob[1024 + c * 3 + 0] = au0 * sc;
    ob[1024 + c * 3 + 1] = au1 * sc;
    ob[1024 + c * 3 + 2] = au2 * sc;
}

// ---------------- launch -----------------------------------------------------
extern "C" void kernel_launch(void* const* d_in, const int* in_sizes, int n_in,
                              void* d_out, int out_size) {
    const float* vectors    = (const float*)d_in[0];
    const float* node_feats = (const float*)d_in[1];
    const float* radial     = (const float*)d_in[2];
    const float* w0         = (const float*)d_in[3];
    const float* w1         = (const float*)d_in[4];
    const float* w2         = (const float*)d_in[5];
    const float* w3         = (const float*)d_in[6];
    const int*   senders    = (const int*)d_in[7];
    const int*   receivers  = (const int*)d_in[8];
    float* out = (float*)d_out;

    int E = in_sizes[0] / 3;
    int N = in_sizes[1] / 512;

    cudaFuncSetAttribute(k_mlp, cudaFuncAttributeMaxDynamicSharedMemorySize,
                         SM_TOTAL);

    k_init<<<(N + 255) / 256, 256>>>(N);
    k_hist<<<(E + 255) / 256, 256>>>(receivers, E);
    k_scan<<<1, 1024>>>(N);
    k_scatter<<<(E + 255) / 256, 256>>>(receivers, E);
    k_w3t<<<(MIXD * 64 + 255) / 256, 256>>>(w3);
    k_mlp<<<(E + 255) / 256, 256, SM_TOTAL>>>(vectors, radial, w0, w1, w2, E);
    k_node<<<N, 128>>>(node_feats, senders, out);
}

// round 6
// speedup vs baseline: 2.1443x; 1.0937x over previous
#include <cuda_runtime.h>
#include <cuda_bf16.h>
#include <cuda_fp16.h>
#include <math.h>
#include <stdint.h>

#define C 128
#define MIXD 640
#define E_MAX 100000
#define N_MAX 10000

typedef unsigned long long u64;

// ---------------- scratch (static device arrays: allocation-free) ----------
__device__ __align__(16) __half g_mix[(size_t)E_MAX * MIXD];   // 128 MB fp16
__device__ __align__(16) __half g_h[(size_t)(E_MAX + 256) * 64];
__device__ __align__(16) float  g_geo[(size_t)E_MAX * 12];
__device__ __align__(16) __half g_w3t[MIXD * 64];              // w3^T/8, fp16
__device__ int g_cnt[N_MAX];
__device__ int g_cur[N_MAX];
__device__ int g_off[N_MAX + 1];
__device__ int g_csr[E_MAX];

// ---------------- f32x2 helpers --------------------------------------------
__device__ __forceinline__ u64 pk2(float x) {
    u64 r; asm("mov.b64 %0,{%1,%1};" : "=l"(r) : "f"(x)); return r;
}
__device__ __forceinline__ void fma2(u64& d, u64 a, u64 b) {
    asm("fma.rn.f32x2 %0, %1, %2, %0;" : "+l"(d) : "l"(a), "l"(b));
}
__device__ __forceinline__ float2 upk(u64 v) {
    float2 r; asm("mov.b64 {%0,%1}, %2;" : "=f"(r.x), "=f"(r.y) : "l"(v)); return r;
}
__device__ __forceinline__ float siluf(float x) { return x / (1.0f + expf(-x)); }

template <int KD>
__device__ __forceinline__ void dense64(const float* __restrict__ W,
                                        const float* in, float* out, float scale) {
#pragma unroll
    for (int t = 0; t < 2; t++) {
        u64 acc[16];
#pragma unroll
        for (int i = 0; i < 16; i++) acc[i] = 0ull;
#pragma unroll
        for (int k = 0; k < KD; k++) {
            u64 hk = pk2(in[k]);
            const ulonglong2* w = (const ulonglong2*)(W + k * 64 + t * 32);
#pragma unroll
            for (int p = 0; p < 8; p++) {
                ulonglong2 u = w[p];
                fma2(acc[2 * p], u.x, hk);
                fma2(acc[2 * p + 1], u.y, hk);
            }
        }
#pragma unroll
        for (int i = 0; i < 16; i++) {
            float2 f = upk(acc[i]);
            out[t * 32 + 2 * i]     = siluf(f.x * scale);
            out[t * 32 + 2 * i + 1] = siluf(f.y * scale);
        }
    }
}

// ---------------- mma / ldmatrix helpers ------------------------------------
__device__ __forceinline__ uint32_t smem_u32(const void* p) {
    uint32_t a;
    asm("{ .reg .u64 t; cvta.to.shared.u64 t, %1; cvt.u32.u64 %0, t; }"
        : "=r"(a) : "l"(p));
    return a;
}
__device__ __forceinline__ void ldm_x4(uint32_t* r, uint32_t addr) {
    asm volatile("ldmatrix.sync.aligned.m8n8.x4.shared.b16 {%0,%1,%2,%3}, [%4];"
                 : "=r"(r[0]), "=r"(r[1]), "=r"(r[2]), "=r"(r[3]) : "r"(addr));
}
__device__ __forceinline__ void mma_f16(float* d, const uint32_t* a,
                                        const uint32_t* b) {
    asm volatile(
        "mma.sync.aligned.m16n8k16.row.col.f32.f16.f16.f32 "
        "{%0,%1,%2,%3}, {%4,%5,%6,%7}, {%8,%9}, {%0,%1,%2,%3};"
        : "+f"(d[0]), "+f"(d[1]), "+f"(d[2]), "+f"(d[3])
        : "r"(a[0]), "r"(a[1]), "r"(a[2]), "r"(a[3]), "r"(b[0]), "r"(b[1]));
}

// ---------------- prep: zero counters + w3 transpose to fp16 ---------------
__global__ void k_prep(const float* __restrict__ w3, int N) {
    int i = blockIdx.x * blockDim.x + threadIdx.x;
    if (i < MIXD * 64) {
        int n = i >> 6, k = i & 63;
        g_w3t[i] = __float2half_rn(w3[k * MIXD + n] * 0.125f);
    }
    if (i < N) { g_cnt[i] = 0; g_cur[i] = 0; }
}
__global__ void k_hist(const int* __restrict__ recv, int E) {
    int i = blockIdx.x * blockDim.x + threadIdx.x;
    if (i < E) atomicAdd(&g_cnt[recv[i]], 1);
}
__global__ void k_scan(int N) {
    __shared__ int wsum[32];
    int tid = threadIdx.x, lane = tid & 31, wid = tid >> 5;
    int per = (N + 1023) >> 10;
    int st = tid * per, en = min(st + per, N);
    int s = 0;
    for (int i = st; i < en; i++) s += g_cnt[i];
    int v = s;
#pragma unroll
    for (int o = 1; o < 32; o <<= 1) {
        int u = __shfl_up_sync(0xffffffffu, v, o);
        if (lane >= o) v += u;
    }
    if (lane == 31) wsum[wid] = v;
    __syncthreads();
    if (wid == 0) {
        int w = wsum[lane];
#pragma unroll
        for (int o = 1; o < 32; o <<= 1) {
            int u = __shfl_up_sync(0xffffffffu, w, o);
            if (lane >= o) w += u;
        }
        wsum[lane] = w;
    }
    __syncthreads();
    int base = (wid > 0 ? wsum[wid - 1] : 0) + (v - s);
    int run = base;
    for (int i = st; i < en; i++) { g_off[i] = run; run += g_cnt[i]; }
    if (tid == 1023) g_off[N] = run;
}
__global__ void k_scatter(const int* __restrict__ recv, int E) {
    int i = blockIdx.x * blockDim.x + threadIdx.x;
    if (i < E) {
        int r = recv[i];
        int p = atomicAdd(&g_cur[r], 1);
        g_csr[g_off[r] + p] = i;
    }
}

// ---------------- k_h: scalar 3-layer MLP -> g_h (fp16) + geometry ---------
__global__ void __launch_bounds__(256) k_h(
    const float* __restrict__ vectors, const float* __restrict__ radial,
    const float* __restrict__ w0, const float* __restrict__ w1,
    const float* __restrict__ w2, int E) {
    __shared__ float ws[8704];  // w0(512) w1(4096) w2(4096)
    int tid = threadIdx.x;
    {
        float4* d = (float4*)ws; const float4* s = (const float4*)w0;
        for (int i = tid; i < 128; i += 256) d[i] = s[i];
        d = (float4*)(ws + 512); s = (const float4*)w1;
        for (int i = tid; i < 1024; i += 256) d[i] = s[i];
        d = (float4*)(ws + 4608); s = (const float4*)w2;
        for (int i = tid; i < 1024; i += 256) d[i] = s[i];
    }

    int e = blockIdx.x * 256 + tid;
    int ec = min(e, E - 1);
    bool valid = (e < E);

    {   // geometry
        float x = vectors[(size_t)ec * 3 + 0];
        float y = vectors[(size_t)ec * 3 + 1];
        float z = vectors[(size_t)ec * 3 + 2];
        float inv = rsqrtf(x * x + y * y + z * z);
        float r0 = x * inv, r1 = y * inv, r2 = z * inv;
        const float SQ3 = 1.7320508075688772f;
        if (valid) {
            float* G = g_geo + (size_t)e * 12;
            G[0] = r0; G[1] = r1; G[2] = r2;
            G[3] = SQ3 * (r0 * r0 - (1.f / 3.f));
            G[4] = SQ3 * r0 * r1;
            G[5] = SQ3 * r0 * r2;
            G[6] = SQ3 * r1 * r0;
            G[7] = SQ3 * (r1 * r1 - (1.f / 3.f));
            G[8] = SQ3 * r1 * r2;
            G[9] = SQ3 * r2 * r0;
            G[10] = SQ3 * r2 * r1;
            G[11] = SQ3 * (r2 * r2 - (1.f / 3.f));
        }
    }

    float rin[8];
    {
        const float4* rp = (const float4*)(radial + (size_t)ec * 8);
        float4 a4 = rp[0], b4 = rp[1];
        rin[0] = a4.x; rin[1] = a4.y; rin[2] = a4.z; rin[3] = a4.w;
        rin[4] = b4.x; rin[5] = b4.y; rin[6] = b4.z; rin[7] = b4.w;
    }
    __syncthreads();

    float a[64], b[64];
    dense64<8>(ws, rin, a, 0.35355339059327373f);
    dense64<64>(ws + 512, a, b, 0.125f);
    dense64<64>(ws + 4608, b, a, 0.125f);

    uint32_t h2[32];
#pragma unroll
    for (int i = 0; i < 32; i++) {
        __half2 p = __floats2half2_rn(a[2 * i], a[2 * i + 1]);
        h2[i] = *(uint32_t*)&p;
    }
    uint4* dst = (uint4*)(g_h + (size_t)e * 64);
#pragma unroll
    for (int j = 0; j < 8; j++) dst[j] = ((uint4*)h2)[j];
}

// ---------------- k_gemm: mix = h @ w3^T via HMMA, coalesced stores ---------
// SMEM: A 256x144 = 36864 | B 80x144 = 11520 | stage 256x176 = 45056
#define GM_A 0
#define GM_B 36864
#define GM_S 48384
#define GM_TOTAL 93440

__global__ void __launch_bounds__(256, 2) k_gemm(int E) {
    extern __shared__ char sm[];
    int tid = threadIdx.x;
    int w = tid >> 5, lane = tid & 31;
    int e0 = blockIdx.x * 256;

    // cooperative A load: 256 rows x 128 B (pitch 144)
    for (int idx = tid; idx < 2048; idx += 256) {
        int row = idx >> 3, seg = idx & 7;
        *(uint4*)(sm + GM_A + row * 144 + seg * 16) =
            ((const uint4*)(g_h + (size_t)(e0 + row) * 64))[seg];
    }
    __syncthreads();

    // persistent A fragments: warp w owns rows 32w..32w+31 (2 m16 tiles)
    uint32_t aF[2][4][4];
    {
        uint32_t Ab = smem_u32(sm + GM_A);
        int g = lane >> 3, r8 = lane & 7;
#pragma unroll
        for (int mt = 0; mt < 2; mt++) {
            int row = 32 * w + 16 * mt + (g & 1) * 8 + r8;
#pragma unroll
            for (int kt = 0; kt < 4; kt++)
                ldm_x4(aF[mt][kt], Ab + (uint32_t)row * 144 + kt * 32 + (g >> 1) * 16);
        }
    }

    uint32_t Bb = smem_u32(sm + GM_B);
    int g = lane >> 3, r8 = lane & 7;
    int m_lane = lane >> 2, n_lane = (lane & 3) * 2;

    for (int cc = 0; cc < 8; cc++) {
        __syncthreads();  // stage/B consumed before overwrite
        for (int idx = tid; idx < 640; idx += 256) {
            int rown = idx >> 3, seg = idx & 7;
            *(uint4*)(sm + GM_B + rown * 144 + seg * 16) =
                *((const uint4*)(g_w3t + (size_t)(cc * 80 + rown) * 64) + seg);
        }
        __syncthreads();

#pragma unroll
        for (int nt = 0; nt < 10; nt++) {
            uint32_t bF[8];
#pragma unroll
            for (int p = 0; p < 2; p++)
                ldm_x4(&bF[p * 4],
                       Bb + (uint32_t)(nt * 8 + r8) * 144 + p * 64 + g * 16);
#pragma unroll
            for (int mt = 0; mt < 2; mt++) {
                float acc[4] = {0.f, 0.f, 0.f, 0.f};
#pragma unroll
                for (int kt = 0; kt < 4; kt++)
                    mma_f16(acc, aF[mt][kt], &bF[kt * 2]);
                int row = 32 * w + 16 * mt + m_lane;
                int cb = (nt * 8 + n_lane) * 2;
                *(__half2*)(sm + GM_S + row * 176 + cb) =
                    __floats2half2_rn(acc[0], acc[1]);
                *(__half2*)(sm + GM_S + (row + 8) * 176 + cb) =
                    __floats2half2_rn(acc[2], acc[3]);
            }
        }
        __syncthreads();

        // coalesced stage -> g_mix (160 B contiguous per edge row)
        for (int idx = tid; idx < 4096; idx += 256) {
            int row = idx >> 4, seg = idx & 15;
            if (seg < 10 && e0 + row < E)
                *(uint4*)(g_mix + (size_t)(e0 + row) * MIXD + cc * 80 + seg * 8) =
                    *(uint4*)(sm + GM_S + row * 176 + seg * 16);
        }
    }
}

// ---------------- per-node gather/accumulate --------------------------------
__global__ void __launch_bounds__(128) k_node(
    const float* __restrict__ nf, const int* __restrict__ senders,
    float* __restrict__ out) {
    int n = blockIdx.x;
    int c = threadIdx.x;
    int beg = g_off[n], end = g_off[n + 1];
    float as0 = 0.f, as1 = 0.f;
    float av0 = 0.f, av1 = 0.f, av2 = 0.f;
    float aw0 = 0.f, aw1 = 0.f, aw2 = 0.f;
    float au0 = 0.f, au1 = 0.f, au2 = 0.f;
    for (int p = beg; p < end; p++) {
        int e = g_csr[p];
        int s = senders[e];
        const float* fr = nf + (size_t)s * 512;
        float ss = fr[c];
        float v0 = fr[128 + c * 3 + 0];
        float v1 = fr[128 + c * 3 + 1];
        float v2 = fr[128 + c * 3 + 2];
        const float4* G = (const float4*)(g_geo + (size_t)e * 12);
        float4 ga = G[0], gb = G[1], gc4 = G[2];
        const __half* mx = g_mix + (size_t)e * MIXD;
        float m0 = __half2float(mx[c]);
        float m1 = __half2float(mx[C + c]);
        float m2 = __half2float(mx[2 * C + c]);
        float m3 = __half2float(mx[3 * C + c]);
        float m4 = __half2float(mx[4 * C + c]);
        float r0 = ga.x, r1 = ga.y, r2 = ga.z;
        float y00 = ga.w, y01 = gb.x, y02 = gb.y, y11 = gb.w,
              y12 = gc4.x, y22 = gc4.w;
        float tp0 = v0 * r0 + v1 * r1 + v2 * r2;
        as0 += ss * m0;
        as1 += tp0 * m1;
        av0 += v0 * m2; av1 += v1 * m2; av2 += v2 * m2;
        float sm3 = ss * m3;
        aw0 += sm3 * r0; aw1 += sm3 * r1; aw2 += sm3 * r2;
        float t0 = y00 * v0 + y01 * v1 + y02 * v2;
        float t1 = y01 * v0 + y11 * v1 + y12 * v2;
        float t2 = y02 * v0 + y12 * v1 + y22 * v2;
        au0 += t0 * m4; au1 += t1 * m4; au2 += t2 * m4;
    }
    const float sc = 0.31622776601683794f;  // 1/sqrt(10)
    float* ob = out + (size_t)n * 1408;
    ob[c] = as0 * sc;
    ob[C + c] = as1 * sc;
    ob[256 + c * 3 + 0] = av0 * sc;
    ob[256 + c * 3 + 1] = av1 * sc;
    ob[256 + c * 3 + 2] = av2 * sc;
    ob[640 + c * 3 + 0] = aw0 * sc;
    ob[640 + c * 3 + 1] = aw1 * sc;
    ob[640 + c * 3 + 2] = aw2 * sc;
    ob[1024 + c * 3 + 0] = au0 * sc;
    ob[1024 + c * 3 + 1] = au1 * sc;
    ob[1024 + c * 3 + 2] = au2 * sc;
}

// ---------------- launch -----------------------------------------------------
extern "C" void kernel_launch(void* const* d_in, const int* in_sizes, int n_in,
                              void* d_out, int out_size) {
    const float* vectors    = (const float*)d_in[0];
    const float* node_feats = (const float*)d_in[1];
    const float* radial     = (const float*)d_in[2];
    const float* w0         = (const float*)d_in[3];
    const float* w1         = (const float*)d_in[4];
    const float* w2         = (const float*)d_in[5];
    const float* w3         = (const float*)d_in[6];
    const int*   senders    = (const int*)d_in[7];
    const int*   receivers  = (const int*)d_in[8];
    float* out = (float*)d_out;

    int E = in_sizes[0] / 3;
    int N = in_sizes[1] / 512;

    cudaFuncSetAttribute(k_gemm, cudaFuncAttributeMaxDynamicSharedMemorySize,
                         GM_TOTAL);

    int nEB = (E + 255) / 256;
    k_prep<<<(MIXD * 64 + 255) / 256, 256>>>(w3, N);
    k_h<<<nEB, 256>>>(vectors, radial, w0, w1, w2, E);
    k_hist<<<(E + 255) / 256, 256>>>(receivers, E);
    k_gemm<<<nEB, 256, GM_TOTAL>>>(E);
    k_scan<<<1, 1024>>>(N);
    k_scatter<<<(E + 255) / 256, 256>>>(receivers, E);
    k_node<<<N, 128>>>(node_feats, senders, out);
}

// round 7
// speedup vs baseline: 2.3123x; 1.0783x over previous
#include <cuda_runtime.h>
#include <cuda_bf16.h>
#include <cuda_fp16.h>
#include <math.h>
#include <stdint.h>

#define C 128
#define MIXD 640
#define E_MAX 100000
#define N_MAX 10000

typedef unsigned long long u64;

// ---------------- scratch (static device arrays: allocation-free) ----------
__device__ __align__(16) __half g_mix[(size_t)E_MAX * MIXD];   // 128 MB fp16
__device__ __align__(16) __half g_h[(size_t)(E_MAX + 256) * 64];
__device__ __align__(16) float  g_geo[(size_t)E_MAX * 12];
__device__ __align__(16) __half g_w3t[MIXD * 64];              // w3^T/8, fp16
__device__ int g_cnt[N_MAX];
__device__ int g_cur[N_MAX];
__device__ int g_off[N_MAX + 1];
__device__ int g_csr[E_MAX];

// ---------------- f32x2 helpers --------------------------------------------
__device__ __forceinline__ u64 pk2(float x) {
    u64 r; asm("mov.b64 %0,{%1,%1};" : "=l"(r) : "f"(x)); return r;
}
__device__ __forceinline__ void fma2(u64& d, u64 a, u64 b) {
    asm("fma.rn.f32x2 %0, %1, %2, %0;" : "+l"(d) : "l"(a), "l"(b));
}
__device__ __forceinline__ float2 upk(u64 v) {
    float2 r; asm("mov.b64 {%0,%1}, %2;" : "=f"(r.x), "=f"(r.y) : "l"(v)); return r;
}
__device__ __forceinline__ float siluf(float x) { return x / (1.0f + expf(-x)); }

template <int KD>
__device__ __forceinline__ void dense64(const float* __restrict__ W,
                                        const float* in, float* out, float scale) {
#pragma unroll
    for (int t = 0; t < 2; t++) {
        u64 acc[16];
#pragma unroll
        for (int i = 0; i < 16; i++) acc[i] = 0ull;
#pragma unroll
        for (int k = 0; k < KD; k++) {
            u64 hk = pk2(in[k]);
            const ulonglong2* w = (const ulonglong2*)(W + k * 64 + t * 32);
#pragma unroll
            for (int p = 0; p < 8; p++) {
                ulonglong2 u = w[p];
                fma2(acc[2 * p], u.x, hk);
                fma2(acc[2 * p + 1], u.y, hk);
            }
        }
#pragma unroll
        for (int i = 0; i < 16; i++) {
            float2 f = upk(acc[i]);
            out[t * 32 + 2 * i]     = siluf(f.x * scale);
            out[t * 32 + 2 * i + 1] = siluf(f.y * scale);
        }
    }
}

// ---------------- mma / ldmatrix helpers ------------------------------------
__device__ __forceinline__ uint32_t smem_u32(const void* p) {
    uint32_t a;
    asm("{ .reg .u64 t; cvta.to.shared.u64 t, %1; cvt.u32.u64 %0, t; }"
        : "=r"(a) : "l"(p));
    return a;
}
__device__ __forceinline__ void ldm_x4(uint32_t* r, uint32_t addr) {
    asm volatile("ldmatrix.sync.aligned.m8n8.x4.shared.b16 {%0,%1,%2,%3}, [%4];"
                 : "=r"(r[0]), "=r"(r[1]), "=r"(r[2]), "=r"(r[3]) : "r"(addr));
}
__device__ __forceinline__ void mma_f16(float* d, const uint32_t* a,
                                        const uint32_t* b) {
    asm volatile(
        "mma.sync.aligned.m16n8k16.row.col.f32.f16.f16.f32 "
        "{%0,%1,%2,%3}, {%4,%5,%6,%7}, {%8,%9}, {%0,%1,%2,%3};"
        : "+f"(d[0]), "+f"(d[1]), "+f"(d[2]), "+f"(d[3])
        : "r"(a[0]), "r"(a[1]), "r"(a[2]), "r"(a[3]), "r"(b[0]), "r"(b[1]));
}

// ---------------- prep: zero counters + w3 transpose to fp16 ---------------
__global__ void k_prep(const float* __restrict__ w3, int N) {
    int i = blockIdx.x * blockDim.x + threadIdx.x;
    if (i < MIXD * 64) {
        int n = i >> 6, k = i & 63;
        g_w3t[i] = __float2half_rn(w3[k * MIXD + n] * 0.125f);
    }
    if (i < N) { g_cnt[i] = 0; g_cur[i] = 0; }
}
__global__ void k_hist(const int* __restrict__ recv, int E) {
    int i = blockIdx.x * blockDim.x + threadIdx.x;
    if (i < E) atomicAdd(&g_cnt[recv[i]], 1);
}
__global__ void k_scan(int N) {
    __shared__ int wsum[32];
    int tid = threadIdx.x, lane = tid & 31, wid = tid >> 5;
    int per = (N + 1023) >> 10;
    int st = tid * per, en = min(st + per, N);
    int s = 0;
    for (int i = st; i < en; i++) s += g_cnt[i];
    int v = s;
#pragma unroll
    for (int o = 1; o < 32; o <<= 1) {
        int u = __shfl_up_sync(0xffffffffu, v, o);
        if (lane >= o) v += u;
    }
    if (lane == 31) wsum[wid] = v;
    __syncthreads();
    if (wid == 0) {
        int w = wsum[lane];
#pragma unroll
        for (int o = 1; o < 32; o <<= 1) {
            int u = __shfl_up_sync(0xffffffffu, w, o);
            if (lane >= o) w += u;
        }
        wsum[lane] = w;
    }
    __syncthreads();
    int base = (wid > 0 ? wsum[wid - 1] : 0) + (v - s);
    int run = base;
    for (int i = st; i < en; i++) { g_off[i] = run; run += g_cnt[i]; }
    if (tid == 1023) g_off[N] = run;
}
__global__ void k_scatter(const int* __restrict__ recv, int E) {
    int i = blockIdx.x * blockDim.x + threadIdx.x;
    if (i < E) {
        int r = recv[i];
        int p = atomicAdd(&g_cur[r], 1);
        g_csr[g_off[r] + p] = i;
    }
}

// ---------------- k_h: scalar 3-layer MLP -> g_h (fp16) + geometry ---------
__global__ void __launch_bounds__(256) k_h(
    const float* __restrict__ vectors, const float* __restrict__ radial,
    const float* __restrict__ w0, const float* __restrict__ w1,
    const float* __restrict__ w2, int E) {
    __shared__ float ws[8704];
    int tid = threadIdx.x;
    {
        float4* d = (float4*)ws; const float4* s = (const float4*)w0;
        for (int i = tid; i < 128; i += 256) d[i] = s[i];
        d = (float4*)(ws + 512); s = (const float4*)w1;
        for (int i = tid; i < 1024; i += 256) d[i] = s[i];
        d = (float4*)(ws + 4608); s = (const float4*)w2;
        for (int i = tid; i < 1024; i += 256) d[i] = s[i];
    }

    int e = blockIdx.x * 256 + tid;
    int ec = min(e, E - 1);
    bool valid = (e < E);

    {   // geometry
        float x = vectors[(size_t)ec * 3 + 0];
        float y = vectors[(size_t)ec * 3 + 1];
        float z = vectors[(size_t)ec * 3 + 2];
        float inv = rsqrtf(x * x + y * y + z * z);
        float r0 = x * inv, r1 = y * inv, r2 = z * inv;
        const float SQ3 = 1.7320508075688772f;
        if (valid) {
            float* G = g_geo + (size_t)e * 12;
            G[0] = r0; G[1] = r1; G[2] = r2;
            G[3] = SQ3 * (r0 * r0 - (1.f / 3.f));
            G[4] = SQ3 * r0 * r1;
            G[5] = SQ3 * r0 * r2;
            G[6] = SQ3 * r1 * r0;
            G[7] = SQ3 * (r1 * r1 - (1.f / 3.f));
            G[8] = SQ3 * r1 * r2;
            G[9] = SQ3 * r2 * r0;
            G[10] = SQ3 * r2 * r1;
            G[11] = SQ3 * (r2 * r2 - (1.f / 3.f));
        }
    }

    float rin[8];
    {
        const float4* rp = (const float4*)(radial + (size_t)ec * 8);
        float4 a4 = rp[0], b4 = rp[1];
        rin[0] = a4.x; rin[1] = a4.y; rin[2] = a4.z; rin[3] = a4.w;
        rin[4] = b4.x; rin[5] = b4.y; rin[6] = b4.z; rin[7] = b4.w;
    }
    __syncthreads();

    float a[64], b[64];
    dense64<8>(ws, rin, a, 0.35355339059327373f);
    dense64<64>(ws + 512, a, b, 0.125f);
    dense64<64>(ws + 4608, b, a, 0.125f);

    uint32_t h2[32];
#pragma unroll
    for (int i = 0; i < 32; i++) {
        __half2 p = __floats2half2_rn(a[2 * i], a[2 * i + 1]);
        h2[i] = *(uint32_t*)&p;
    }
    uint4* dst = (uint4*)(g_h + (size_t)e * 64);
#pragma unroll
    for (int j = 0; j < 8; j++) dst[j] = ((uint4*)h2)[j];
}

// ---------------- k_gemm: mix = h @ w3^T via HMMA ---------------------------
// SMEM: A 256x144 = 36864 (REUSED as 128x176 stage) | B 80x144 = 11520
#define GM_A 0
#define GM_B 36864
#define GM_TOTAL 48384

__global__ void __launch_bounds__(256, 3) k_gemm(int E) {
    extern __shared__ char sm[];
    int tid = threadIdx.x;
    int w = tid >> 5, lane = tid & 31;
    int e0 = blockIdx.x * 256;

    // cooperative A load: 256 rows x 128 B (pitch 144)
    for (int idx = tid; idx < 2048; idx += 256) {
        int row = idx >> 3, seg = idx & 7;
        *(uint4*)(sm + GM_A + row * 144 + seg * 16) =
            ((const uint4*)(g_h + (size_t)(e0 + row) * 64))[seg];
    }
    __syncthreads();

    // persistent A fragments: warp w owns rows 32w..32w+31 (2 m16 tiles)
    uint32_t aF[2][4][4];
    {
        uint32_t Ab = smem_u32(sm + GM_A);
        int g = lane >> 3, r8 = lane & 7;
#pragma unroll
        for (int mt = 0; mt < 2; mt++) {
            int row = 32 * w + 16 * mt + (g & 1) * 8 + r8;
#pragma unroll
            for (int kt = 0; kt < 4; kt++)
                ldm_x4(aF[mt][kt], Ab + (uint32_t)row * 144 + kt * 32 + (g >> 1) * 16);
        }
    }
    __syncthreads();  // all aF reads done; A region becomes the stage

    uint32_t Bb = smem_u32(sm + GM_B);
    int g = lane >> 3, r8 = lane & 7;
    int m_lane = lane >> 2, n_lane = (lane & 3) * 2;

    for (int cc = 0; cc < 8; cc++) {
        // load B tile for this 80-column chunk
        for (int idx = tid; idx < 640; idx += 256) {
            int rown = idx >> 3, seg = idx & 7;
            *(uint4*)(sm + GM_B + rown * 144 + seg * 16) =
                *((const uint4*)(g_w3t + (size_t)(cc * 80 + rown) * 64) + seg);
        }
        __syncthreads();

#pragma unroll
        for (int mt = 0; mt < 2; mt++) {
#pragma unroll
            for (int nt = 0; nt < 10; nt++) {
                uint32_t bF[8];
#pragma unroll
                for (int p = 0; p < 2; p++)
                    ldm_x4(&bF[p * 4],
                           Bb + (uint32_t)(nt * 8 + r8) * 144 + p * 64 + g * 16);
                float acc[4] = {0.f, 0.f, 0.f, 0.f};
#pragma unroll
                for (int kt = 0; kt < 4; kt++)
                    mma_f16(acc, aF[mt][kt], &bF[kt * 2]);
                int srow = w * 16 + m_lane;   // stage row (16 per warp)
                int cb = (nt * 8 + n_lane) * 2;
                *(__half2*)(sm + GM_A + srow * 176 + cb) =
                    __floats2half2_rn(acc[0], acc[1]);
                *(__half2*)(sm + GM_A + (srow + 8) * 176 + cb) =
                    __floats2half2_rn(acc[2], acc[3]);
            }
            __syncthreads();
            // coalesced stage -> g_mix (160 B contiguous per edge row)
            for (int idx = tid; idx < 2048; idx += 256) {
                int srow = idx >> 4, seg = idx & 15;
                int grow = e0 + 32 * (srow >> 4) + 16 * mt + (srow & 15);
                if (seg < 10 && grow < E)
                    *(uint4*)(g_mix + (size_t)grow * MIXD + cc * 80 + seg * 8) =
                        *(uint4*)(sm + GM_A + srow * 176 + seg * 16);
            }
            __syncthreads();
        }
    }
}

// ---------------- per-node gather: 2 edge-groups + index prefetch -----------
#define CHUNK 64
__global__ void __launch_bounds__(256) k_node(
    const float* __restrict__ nf, const int* __restrict__ senders,
    float* __restrict__ out) {
    __shared__ int sE[CHUNK], sS[CHUNK];
    __shared__ float red[11 * 128];
    int n = blockIdx.x;
    int tid = threadIdx.x;
    int c = tid & 127, grp = tid >> 7;
    int beg = g_off[n], end = g_off[n + 1];

    float as0 = 0.f, as1 = 0.f;
    float av0 = 0.f, av1 = 0.f, av2 = 0.f;
    float aw0 = 0.f, aw1 = 0.f, aw2 = 0.f;
    float au0 = 0.f, au1 = 0.f, au2 = 0.f;

    for (int ch = beg; ch < end; ch += CHUNK) {
        int cnt = min(CHUNK, end - ch);
        __syncthreads();
        if (tid < cnt) {
            int e = g_csr[ch + tid];
            sE[tid] = e;
            sS[tid] = senders[e];
        }
        __syncthreads();
        for (int i = grp; i < cnt; i += 2) {
            int e = sE[i];
            int s = sS[i];
            const float* fr = nf + (size_t)s * 512;
            float ss = fr[c];
            float v0 = fr[128 + c * 3 + 0];
            float v1 = fr[128 + c * 3 + 1];
            float v2 = fr[128 + c * 3 + 2];
            const float4* G = (const float4*)(g_geo + (size_t)e * 12);
            float4 ga = G[0], gb = G[1], gc4 = G[2];
            const __half* mx = g_mix + (size_t)e * MIXD;
            float m0 = __half2float(mx[c]);
            float m1 = __half2float(mx[C + c]);
            float m2 = __half2float(mx[2 * C + c]);
            float m3 = __half2float(mx[3 * C + c]);
            float m4 = __half2float(mx[4 * C + c]);
            float r0 = ga.x, r1 = ga.y, r2 = ga.z;
            float y00 = ga.w, y01 = gb.x, y02 = gb.y, y11 = gb.w,
                  y12 = gc4.x, y22 = gc4.w;
            float tp0 = v0 * r0 + v1 * r1 + v2 * r2;
            as0 += ss * m0;
            as1 += tp0 * m1;
            av0 += v0 * m2; av1 += v1 * m2; av2 += v2 * m2;
            float sm3 = ss * m3;
            aw0 += sm3 * r0; aw1 += sm3 * r1; aw2 += sm3 * r2;
            float t0 = y00 * v0 + y01 * v1 + y02 * v2;
            float t1 = y01 * v0 + y11 * v1 + y12 * v2;
            float t2 = y02 * v0 + y12 * v1 + y22 * v2;
            au0 += t0 * m4; au1 += t1 * m4; au2 += t2 * m4;
        }
    }

    // group 1 publishes partials, group 0 combines + writes
    if (grp == 1) {
        red[c] = as0;            red[128 + c] = as1;
        red[256 + c] = av0;      red[384 + c] = av1;  red[512 + c] = av2;
        red[640 + c] = aw0;      red[768 + c] = aw1;  red[896 + c] = aw2;
        red[1024 + c] = au0;     red[1152 + c] = au1; red[1280 + c] = au2;
    }
    __syncthreads();
    if (grp == 0) {
        as0 += red[c];           as1 += red[128 + c];
        av0 += red[256 + c];     av1 += red[384 + c]; av2 += red[512 + c];
        aw0 += red[640 + c];     aw1 += red[768 + c]; aw2 += red[896 + c];
        au0 += red[1024 + c];    au1 += red[1152 + c]; au2 += red[1280 + c];
        const float sc = 0.31622776601683794f;  // 1/sqrt(10)
        float* ob = out + (size_t)n * 1408;
        ob[c] = as0 * sc;
        ob[C + c] = as1 * sc;
        ob[256 + c * 3 + 0] = av0 * sc;
        ob[256 + c * 3 + 1] = av1 * sc;
        ob[256 + c * 3 + 2] = av2 * sc;
        ob[640 + c * 3 + 0] = aw0 * sc;
        ob[640 + c * 3 + 1] = aw1 * sc;
        ob[640 + c * 3 + 2] = aw2 * sc;
        ob[1024 + c * 3 + 0] = au0 * sc;
        ob[1024 + c * 3 + 1] = au1 * sc;
        ob[1024 + c * 3 + 2] = au2 * sc;
    }
}

// ---------------- launch -----------------------------------------------------
extern "C" void kernel_launch(void* const* d_in, const int* in_sizes, int n_in,
                              void* d_out, int out_size) {
    const float* vectors    = (const float*)d_in[0];
    const float* node_feats = (const float*)d_in[1];
    const float* radial     = (const float*)d_in[2];
    const float* w0         = (const float*)d_in[3];
    const float* w1         = (const float*)d_in[4];
    const float* w2         = (const float*)d_in[5];
    const float* w3         = (const float*)d_in[6];
    const int*   senders    = (const int*)d_in[7];
    const int*   receivers  = (const int*)d_in[8];
    float* out = (float*)d_out;

    int E = in_sizes[0] / 3;
    int N = in_sizes[1] / 512;

    cudaFuncSetAttribute(k_gemm, cudaFuncAttributeMaxDynamicSharedMemorySize,
                         GM_TOTAL);

    int nEB = (E + 255) / 256;
    k_prep<<<(MIXD * 64 + 255) / 256, 256>>>(w3, N);
    k_h<<<nEB, 256>>>(vectors, radial, w0, w1, w2, E);
    k_hist<<<(E + 255) / 256, 256>>>(receivers, E);
    k_gemm<<<nEB, 256, GM_TOTAL>>>(E);
    k_scan<<<1, 1024>>>(N);
    k_scatter<<<(E + 255) / 256, 256>>>(receivers, E);
    k_node<<<N, 256>>>(node_feats, senders, out);
}